// round 15
// baseline (speedup 1.0000x reference)
#include <cuda_runtime.h>
#include <cuda_bf16.h>
#include <cstdint>

// ============================================================================
// MajFC via bit-plane majority:
//   mismatch bits m_j = xb_j ^ wb_j  ->  clip(sum,-1,1) = 1 - 2*MAJ(m0,m1,m2)
//   out = 2304 - 4.5*T,  T = #groups with MAJ = 1.
// Row layout: 8 supergroups x 12 words (3 planes x 4 block-words), K = 96.
// R15: whole-K SMEM staging in ONE cp.async round -> a single __syncthreads
// per CTA; all 8 supergroups computed barrier-free. Direct output, no atomics.
// ============================================================================

#define BROWS 256
#define CIN   3072
#define COUT  1024
#define KWP   96
#define NSG   8

__device__ __align__(16) uint32_t g_Xb[BROWS * KWP];          // 96 KB
__device__ __align__(16) uint32_t g_Wb[COUT  * KWP];          // 384 KB

__device__ __forceinline__ uint32_t maj3(uint32_t a, uint32_t b, uint32_t c) {
    uint32_t r;
    asm("lop3.b32 %0, %1, %2, %3, 0xE8;" : "=r"(r) : "r"(a), "r"(b), "r"(c));
    return r;
}

// ---------------------------------------------------------------------------
// Pack (R12): one warp = 768 floats (256 groups = 8 blocks) of one row.
// ---------------------------------------------------------------------------
#define SEGS 4
#define PACK_TASKS ((BROWS + COUT) * SEGS)       // 5120 warps

__global__ void __launch_bounds__(256) pack_kernel(const float* __restrict__ x,
                                                   const float* __restrict__ w) {
    int task = (blockIdx.x * blockDim.x + threadIdx.x) >> 5;
    int lane = threadIdx.x & 31;
    int row = task >> 2, seg = task & 3;

    const float* src;
    uint32_t*    dst;
    if (row < BROWS) {
        src = x + (size_t)row * CIN;
        dst = g_Xb + (size_t)row * KWP;
    } else {
        src = w + (size_t)(row - BROWS) * CIN;
        dst = g_Wb + (size_t)(row - BROWS) * KWP;
    }
    const float* base = src + seg * 768 + lane * 3;

    unsigned c0[8], c1[8], c2[8];
#pragma unroll
    for (int b = 0; b < 8; b++) {
        const float* p = base + b * 96;
        c0[b] = p[0] > 0.f;
        c1[b] = p[1] > 0.f;
        c2[b] = p[2] > 0.f;
    }
    unsigned my = 0;
#pragma unroll
    for (int b = 0; b < 8; b++) {
        unsigned w0 = __ballot_sync(0xFFFFFFFFu, c0[b]);
        unsigned w1 = __ballot_sync(0xFFFFFFFFu, c1[b]);
        unsigned w2 = __ballot_sync(0xFFFFFFFFu, c2[b]);
        if (lane == b)      my = w0;
        if (lane == 8 + b)  my = w1;
        if (lane == 16 + b) my = w2;
    }
    if (lane < 24) {
        int j = lane >> 3, bl = lane & 7;
        int gb = seg * 8 + bl;
        dst[(gb >> 2) * 12 + j * 4 + (gb & 3)] = my;
    }
}

// ---------------------------------------------------------------------------
// cp.async helpers.
// ---------------------------------------------------------------------------
__device__ __forceinline__ void cp16(uint32_t smem, const void* gmem) {
    asm volatile("cp.async.cg.shared.global [%0], [%1], 16;"
                 :: "r"(smem), "l"(gmem));
}
__device__ __forceinline__ void cp_commit() {
    asm volatile("cp.async.commit_group;");
}
__device__ __forceinline__ void cp_wait0() {
    asm volatile("cp.async.wait_group 0;");
}

// ---------------------------------------------------------------------------
// Full-K majority GEMM, one-shot staging. Tile 16(m) x 32(n), 128 threads,
// grid = 512. SMEM: 48 rows x 96 words, pitch 100 (400 B = 25 16B-units;
// 25 mod 8 = 1 -> W-row reads across ni are a bank permutation, conflict-
// free; X reads phase-broadcast). One commit/wait/syncthreads total.
// ---------------------------------------------------------------------------
#define TM 16
#define TN 32
#define SPX 100

__global__ void __launch_bounds__(128) maj_gemm_kernel(float* __restrict__ out) {
    __shared__ __align__(16) uint32_t S[48][SPX];    // 18.75 KB

    int tid = threadIdx.x;
    int bid = blockIdx.x;
    int m0 = (bid >> 5) * TM;             // 16 m-tiles
    int n0 = (bid & 31) * TN;             // 32 n-tiles
    int mi = tid >> 3;                    // 0..15 -> one m row
    int ni = tid & 7;                     // 0..7  -> n cols ni + 8c

    uint32_t sbase = (uint32_t)__cvta_generic_to_shared(&S[0][0]);

    // Stage ALL of K: 48 rows x 24 uint4 = 1152 cp16, 9 per thread.
#pragma unroll
    for (int p = 0; p < 9; p++) {
        int idx = p * 128 + tid;
        int r = idx / 24, c = (idx % 24) * 4;
        const uint32_t* g = (r < TM)
            ? &g_Xb[(size_t)(m0 + r) * KWP + c]
            : &g_Wb[(size_t)(n0 + r - TM) * KWP + c];
        cp16(sbase + (uint32_t)(r * SPX + c) * 4, g);
    }
    cp_commit();
    cp_wait0();
    __syncthreads();                      // the ONLY barrier

    int acc0 = 0, acc1 = 0, acc2 = 0, acc3 = 0;

#pragma unroll
    for (int s = 0; s < NSG; s++) {
        const uint32_t* xr = &S[mi][s * 12];
        uint4 x0 = *reinterpret_cast<const uint4*>(xr);
        uint4 x1 = *reinterpret_cast<const uint4*>(xr + 4);
        uint4 x2 = *reinterpret_cast<const uint4*>(xr + 8);
        const uint32_t* xp0 = reinterpret_cast<const uint32_t*>(&x0);
        const uint32_t* xp1 = reinterpret_cast<const uint32_t*>(&x1);
        const uint32_t* xp2 = reinterpret_cast<const uint32_t*>(&x2);
#pragma unroll
        for (int c = 0; c < 4; c++) {
            const uint32_t* wr = &S[TM + ni + c * 8][s * 12];
            uint4 w0 = *reinterpret_cast<const uint4*>(wr);
            uint4 w1 = *reinterpret_cast<const uint4*>(wr + 4);
            uint4 w2 = *reinterpret_cast<const uint4*>(wr + 8);
            const uint32_t* wp0 = reinterpret_cast<const uint32_t*>(&w0);
            const uint32_t* wp1 = reinterpret_cast<const uint32_t*>(&w1);
            const uint32_t* wp2 = reinterpret_cast<const uint32_t*>(&w2);
            int a = 0;
#pragma unroll
            for (int e = 0; e < 4; e++)
                a += __popc(maj3(xp0[e] ^ wp0[e],
                                 xp1[e] ^ wp1[e],
                                 xp2[e] ^ wp2[e]));
            if      (c == 0) acc0 += a;
            else if (c == 1) acc1 += a;
            else if (c == 2) acc2 += a;
            else             acc3 += a;
        }
    }

    // out = 2.25 * (1024 - 2T) = 2304 - 4.5*T
    float* o = out + (size_t)(m0 + mi) * COUT + n0 + ni;
    o[0]  = 2304.0f - 4.5f * (float)acc0;
    o[8]  = 2304.0f - 4.5f * (float)acc1;
    o[16] = 2304.0f - 4.5f * (float)acc2;
    o[24] = 2304.0f - 4.5f * (float)acc3;
}

// ---------------------------------------------------------------------------
extern "C" void kernel_launch(void* const* d_in, const int* in_sizes, int n_in,
                              void* d_out, int out_size) {
    const float* x = (const float*)d_in[0];   // [256, 3072]
    const float* w = (const float*)d_in[1];   // [1024, 3072]
    float* out = (float*)d_out;               // [256, 1024] float32

    pack_kernel<<<PACK_TASKS * 32 / 256, 256>>>(x, w);
    maj_gemm_kernel<<<512, 128>>>(out);
}

// round 16
// speedup vs baseline: 1.0201x; 1.0201x over previous
#include <cuda_runtime.h>
#include <cuda_bf16.h>
#include <cstdint>

// ============================================================================
// MajFC via bit-plane majority:
//   mismatch bits m_j = xb_j ^ wb_j  ->  clip(sum,-1,1) = 1 - 2*MAJ(m0,m1,m2)
//   out = 2304 - 4.5*T,  T = #groups with MAJ = 1.
// Row layout: 8 supergroups x 12 words (3 planes x 4 block-words), K = 96.
// R16: tile 16x16 -> 1024 CTAs (2x warps/SM); one-shot cp.async staging,
// single barrier, direct output. Independent accumulators for ILP.
// ============================================================================

#define BROWS 256
#define CIN   3072
#define COUT  1024
#define KWP   96
#define NSG   8

__device__ __align__(16) uint32_t g_Xb[BROWS * KWP];          // 96 KB
__device__ __align__(16) uint32_t g_Wb[COUT  * KWP];          // 384 KB

__device__ __forceinline__ uint32_t maj3(uint32_t a, uint32_t b, uint32_t c) {
    uint32_t r;
    asm("lop3.b32 %0, %1, %2, %3, 0xE8;" : "=r"(r) : "r"(a), "r"(b), "r"(c));
    return r;
}

// ---------------------------------------------------------------------------
// Pack (R12): one warp = 768 floats (256 groups = 8 blocks) of one row.
// ---------------------------------------------------------------------------
#define SEGS 4
#define PACK_TASKS ((BROWS + COUT) * SEGS)       // 5120 warps

__global__ void __launch_bounds__(256) pack_kernel(const float* __restrict__ x,
                                                   const float* __restrict__ w) {
    int task = (blockIdx.x * blockDim.x + threadIdx.x) >> 5;
    int lane = threadIdx.x & 31;
    int row = task >> 2, seg = task & 3;

    const float* src;
    uint32_t*    dst;
    if (row < BROWS) {
        src = x + (size_t)row * CIN;
        dst = g_Xb + (size_t)row * KWP;
    } else {
        src = w + (size_t)(row - BROWS) * CIN;
        dst = g_Wb + (size_t)(row - BROWS) * KWP;
    }
    const float* base = src + seg * 768 + lane * 3;

    unsigned c0[8], c1[8], c2[8];
#pragma unroll
    for (int b = 0; b < 8; b++) {
        const float* p = base + b * 96;
        c0[b] = p[0] > 0.f;
        c1[b] = p[1] > 0.f;
        c2[b] = p[2] > 0.f;
    }
    unsigned my = 0;
#pragma unroll
    for (int b = 0; b < 8; b++) {
        unsigned w0 = __ballot_sync(0xFFFFFFFFu, c0[b]);
        unsigned w1 = __ballot_sync(0xFFFFFFFFu, c1[b]);
        unsigned w2 = __ballot_sync(0xFFFFFFFFu, c2[b]);
        if (lane == b)      my = w0;
        if (lane == 8 + b)  my = w1;
        if (lane == 16 + b) my = w2;
    }
    if (lane < 24) {
        int j = lane >> 3, bl = lane & 7;
        int gb = seg * 8 + bl;
        dst[(gb >> 2) * 12 + j * 4 + (gb & 3)] = my;
    }
}

// ---------------------------------------------------------------------------
// cp.async helpers.
// ---------------------------------------------------------------------------
__device__ __forceinline__ void cp16(uint32_t smem, const void* gmem) {
    asm volatile("cp.async.cg.shared.global [%0], [%1], 16;"
                 :: "r"(smem), "l"(gmem));
}
__device__ __forceinline__ void cp_commit() {
    asm volatile("cp.async.commit_group;");
}
__device__ __forceinline__ void cp_wait0() {
    asm volatile("cp.async.wait_group 0;");
}

// ---------------------------------------------------------------------------
// Full-K majority GEMM. Tile 16(m) x 16(n), 128 threads, 2 outputs/thread,
// grid = 1024 (~28 warps/SM). SMEM: 32 rows x 96 words, pitch 100 (25 16B
// units, odd -> W-row reads across ni are a bank permutation; X broadcast).
// One cp.async round, one barrier, direct output.
// ---------------------------------------------------------------------------
#define TM 16
#define TN 16
#define SPX 100

__global__ void __launch_bounds__(128) maj_gemm_kernel(float* __restrict__ out) {
    __shared__ __align__(16) uint32_t S[32][SPX];    // 12.5 KB

    int tid = threadIdx.x;
    int bid = blockIdx.x;
    int m0 = (bid >> 6) * TM;             // 16 m-tiles
    int n0 = (bid & 63) * TN;             // 64 n-tiles
    int mi = tid >> 3;                    // 0..15 -> one m row
    int ni = tid & 7;                     // 0..7  -> n cols ni, ni+8

    uint32_t sbase = (uint32_t)__cvta_generic_to_shared(&S[0][0]);

    // Stage ALL of K: 32 rows x 24 uint4 = 768 cp16, 6 per thread.
#pragma unroll
    for (int p = 0; p < 6; p++) {
        int idx = p * 128 + tid;
        int r = idx / 24, c = (idx % 24) * 4;
        const uint32_t* g = (r < TM)
            ? &g_Xb[(size_t)(m0 + r) * KWP + c]
            : &g_Wb[(size_t)(n0 + r - TM) * KWP + c];
        cp16(sbase + (uint32_t)(r * SPX + c) * 4, g);
    }
    cp_commit();
    cp_wait0();
    __syncthreads();                      // the ONLY barrier

    // Independent accumulators (per output x per e-slot) to break IADD chains.
    int a0[4] = {}, a1[4] = {};

#pragma unroll
    for (int s = 0; s < NSG; s++) {
        const uint32_t* xr = &S[mi][s * 12];
        uint4 x0 = *reinterpret_cast<const uint4*>(xr);
        uint4 x1 = *reinterpret_cast<const uint4*>(xr + 4);
        uint4 x2 = *reinterpret_cast<const uint4*>(xr + 8);
        const uint32_t* xp0 = reinterpret_cast<const uint32_t*>(&x0);
        const uint32_t* xp1 = reinterpret_cast<const uint32_t*>(&x1);
        const uint32_t* xp2 = reinterpret_cast<const uint32_t*>(&x2);
#pragma unroll
        for (int c = 0; c < 2; c++) {
            const uint32_t* wr = &S[TM + ni + c * 8][s * 12];
            uint4 w0 = *reinterpret_cast<const uint4*>(wr);
            uint4 w1 = *reinterpret_cast<const uint4*>(wr + 4);
            uint4 w2 = *reinterpret_cast<const uint4*>(wr + 8);
            const uint32_t* wp0 = reinterpret_cast<const uint32_t*>(&w0);
            const uint32_t* wp1 = reinterpret_cast<const uint32_t*>(&w1);
            const uint32_t* wp2 = reinterpret_cast<const uint32_t*>(&w2);
            int* acc = c ? a1 : a0;
#pragma unroll
            for (int e = 0; e < 4; e++)
                acc[e] += __popc(maj3(xp0[e] ^ wp0[e],
                                      xp1[e] ^ wp1[e],
                                      xp2[e] ^ wp2[e]));
        }
    }

    // out = 2.25 * (1024 - 2T) = 2304 - 4.5*T
    float* o = out + (size_t)(m0 + mi) * COUT + n0 + ni;
    o[0] = 2304.0f - 4.5f * (float)(a0[0] + a0[1] + a0[2] + a0[3]);
    o[8] = 2304.0f - 4.5f * (float)(a1[0] + a1[1] + a1[2] + a1[3]);
}

// ---------------------------------------------------------------------------
extern "C" void kernel_launch(void* const* d_in, const int* in_sizes, int n_in,
                              void* d_out, int out_size) {
    const float* x = (const float*)d_in[0];   // [256, 3072]
    const float* w = (const float*)d_in[1];   // [1024, 3072]
    float* out = (float*)d_out;               // [256, 1024] float32

    pack_kernel<<<PACK_TASKS * 32 / 256, 256>>>(x, w);
    maj_gemm_kernel<<<1024, 128>>>(out);
}